// round 7
// baseline (speedup 1.0000x reference)
#include <cuda_runtime.h>
#include <cuda_bf16.h>
#include <cstdint>

// Per-pixel dynamic 5x5 conv, channel-shared taps.
// x: [B=8, C=64, H=256, W=256] f32; w: [25, B, 1, H, W] f32
//
// 2x2 pixel quad per thread, 128 threads/CTA (16x32 tile), 100 weight regs
// (as 50 packed f32x2 pairs) reused across 32 channels. All tap math uses
// fma.rn.f32x2 (FFMA2): 50 packed FMAs/thread/channel instead of 100 FFMA.
// 4-stage cp.async ring (distance 2), one barrier/channel, 3 CTAs/SM.

#define BB 8
#define HW 65536
#define HH_DIM 256
#define WW_DIM 256
#define TH 16
#define TW 32
#define SMH (TH + 4)          // 20
#define SMCOLS (TW + 4)       // 36
#define SMW 40                // row stride (floats)
#define SMSZ (SMH * SMW)      // 800 floats per stage
#define NLOAD (SMH * SMCOLS)  // 720
#define NSLOT 6
#define CPERCTA 32
#define NSTAGE 4

__device__ __forceinline__ void cp_async4(uint32_t saddr, const void* gaddr, int src_size) {
    asm volatile("cp.async.ca.shared.global [%0], [%1], 4, %2;"
                 :: "r"(saddr), "l"(gaddr), "r"(src_size));
}
__device__ __forceinline__ void cp_commit() {
    asm volatile("cp.async.commit_group;");
}
template <int N>
__device__ __forceinline__ void cp_wait() {
    asm volatile("cp.async.wait_group %0;" :: "n"(N));
}

// ---- packed fp32x2 helpers ----
__device__ __forceinline__ uint64_t lds64(uint32_t a) {
    uint64_t v; asm volatile("ld.shared.b64 %0, [%1];" : "=l"(v) : "r"(a)); return v;
}
__device__ __forceinline__ void ffma2(uint64_t& d, uint64_t a, uint64_t b) {
    asm("fma.rn.f32x2 %0, %1, %2, %0;" : "+l"(d) : "l"(a), "l"(b));
}
__device__ __forceinline__ uint64_t addf32x2(uint64_t a, uint64_t b) {
    uint64_t r; asm("add.rn.f32x2 %0, %1, %2;" : "=l"(r) : "l"(a), "l"(b)); return r;
}
__device__ __forceinline__ uint64_t pack2(uint32_t lo, uint32_t hi) {
    uint64_t r; asm("mov.b64 %0, {%1, %2};" : "=l"(r) : "r"(lo), "r"(hi)); return r;
}
__device__ __forceinline__ void unpack2(uint64_t v, uint32_t& lo, uint32_t& hi) {
    asm("mov.b64 {%0, %1}, %2;" : "=r"(lo), "=r"(hi) : "l"(v));
}

__global__ __launch_bounds__(128, 3)
void dynconv5x5_kernel(const float* __restrict__ x,
                       const float* __restrict__ wgt,
                       float* __restrict__ out) {
    __shared__ float sm[NSTAGE][SMSZ];

    const int tid = threadIdx.x;
    const int qx  = tid & 15;
    const int qy  = tid >> 4;
    const int w0  = blockIdx.x * TW;
    const int h0  = blockIdx.y * TH;
    const int z   = blockIdx.z;
    const int b   = z >> 1;
    const int c0  = (z & 1) * CPERCTA;

    const int oh = h0 + qy * 2;
    const int ow = w0 + qx * 2;   // even -> 8B aligned everywhere

    // ---- quad weights as packed pairs: wt[k]={w(px0),w(px1)} top row, wb bottom
    uint64_t wt[25], wb[25];
#pragma unroll
    for (int k = 0; k < 25; k++) {
        const float* wp = &wgt[(((size_t)k * BB + b) * HH_DIM + oh) * WW_DIM + ow];
        wt[k] = *(const uint64_t*)(wp);
        wb[k] = *(const uint64_t*)(wp + WW_DIM);
    }

    // ---- hoisted staging slots
    int xoff[NSLOT];
    int ssz [NSLOT];
    int soff[NSLOT];   // bytes
#pragma unroll
    for (int j = 0; j < NSLOT; j++) {
        int i  = tid + j * 128;
        int r  = i / SMCOLS;
        int cc = i - r * SMCOLS;
        bool act = (i < NLOAD);
        int gh = h0 + r - 2;
        int gw = w0 + cc - 2;
        bool v = act && gh >= 0 && gh < HH_DIM && gw >= 0 && gw < WW_DIM;
        xoff[j] = gh * WW_DIM + gw;
        ssz[j]  = v ? 4 : 0;
        soff[j] = (act ? (r * SMW + cc) : (SMSZ - 1)) * 4;
    }

    const float* xc = x   + ((size_t)b * 64 + c0) * HW;
    float*       ob = out + (((size_t)b * 64 + c0) * HW) + oh * WW_DIM + ow;

    // per-stage lane base addresses for compute reads
    const uint32_t laneoff = ((qy * 2) * SMW + qx * 2) * 4;
    uint32_t sb[NSTAGE], sab[NSTAGE];
#pragma unroll
    for (int s = 0; s < NSTAGE; s++) {
        sb[s]  = (uint32_t)__cvta_generic_to_shared(&sm[s][0]);
        sab[s] = sb[s] + laneoff;
    }

    // ---- prologue: stage channels 0 and 1
#pragma unroll
    for (int p = 0; p < 2; p++) {
        const float* xp = xc + (size_t)p * HW;
#pragma unroll
        for (int j = 0; j < NSLOT; j++)
            cp_async4(sb[p] + soff[j], xp + xoff[j], ssz[j]);
        cp_commit();
    }

#pragma unroll 4
    for (int c = 0; c < CPERCTA; c++) {
        if (c + 2 < CPERCTA) cp_wait<1>(); else cp_wait<0>();
        __syncthreads();

        const uint32_t sbase = sab[c & (NSTAGE - 1)];

        // ---- 25 taps x 4 px via packed f32x2: 4 packed accumulator chains
        uint64_t at_e = 0, at_o = 0, ab_e = 0, ab_o = 0;
#pragma unroll
        for (int r = 0; r < 6; r++) {
            uint32_t base = sbase + r * (SMW * 4);
            uint64_t p0 = lds64(base);        // {x0,x1}
            uint64_t p2 = lds64(base + 8);    // {x2,x3}
            uint64_t p4 = lds64(base + 16);   // {x4,x5}
            uint32_t x0, x1, x2, x3, x4, x5;
            unpack2(p0, x0, x1);
            unpack2(p2, x2, x3);
            unpack2(p4, x4, x5);
            uint64_t p1 = pack2(x1, x2);      // {x1,x2}
            uint64_t p3 = pack2(x3, x4);      // {x3,x4}
            uint64_t P[5] = {p0, p1, p2, p3, p4};
            if (r < 5) {
#pragma unroll
                for (int ww = 0; ww < 5; ww++) {
                    int k = r * 5 + ww;
                    ffma2((k & 1) ? at_o : at_e, P[ww], wt[k]);
                }
            }
            if (r >= 1) {
#pragma unroll
                for (int ww = 0; ww < 5; ww++) {
                    int k = (r - 1) * 5 + ww;
                    ffma2((k & 1) ? ab_o : ab_e, P[ww], wb[k]);
                }
            }
        }

        float* o = ob + (size_t)c * HW;
        *(uint64_t*)(o)          = addf32x2(at_e, at_o);
        *(uint64_t*)(o + WW_DIM) = addf32x2(ab_e, ab_o);

        if (c + 2 < CPERCTA) {
            const float* xn = xc + (size_t)(c + 2) * HW;
            const uint32_t sbn = sb[(c + 2) & (NSTAGE - 1)];
#pragma unroll
            for (int j = 0; j < NSLOT; j++)
                cp_async4(sbn + soff[j], xn + xoff[j], ssz[j]);
            cp_commit();
        }
    }
}

extern "C" void kernel_launch(void* const* d_in, const int* in_sizes, int n_in,
                              void* d_out, int out_size) {
    const float* x   = (const float*)d_in[0];
    const float* wgt = (const float*)d_in[1];
    float*       out = (float*)d_out;

    dim3 grid(WW_DIM / TW, HH_DIM / TH, BB * 2);   // 2048 blocks
    dim3 block(128);
    dynconv5x5_kernel<<<grid, block>>>(x, wgt, out);
}

// round 8
// speedup vs baseline: 1.0240x; 1.0240x over previous
#include <cuda_runtime.h>
#include <cuda_bf16.h>
#include <cstdint>

// Per-pixel dynamic 5x5 conv, channel-shared taps.
// x: [B=8, C=64, H=256, W=256] f32; w: [25, B, 1, H, W] f32
//
// WARP-PRIVATE pipelines: each of the 4 warps in a CTA owns 4 output rows and
// stages its own 8-row x 36-col input slab through a private 4-stage cp.async
// ring. No __syncthreads anywhere in the channel loop -- only __syncwarp.
// 2x2 quad/thread, 100 weight regs as 50 packed f32x2, FFMA2 math,
// prefetch distance 3, 3 CTAs/SM.

#define BB 8
#define HW 65536
#define HH_DIM 256
#define WW_DIM 256
#define TH 16
#define TW 32
#define SMCOLS (TW + 4)       // 36 valid cols
#define SMW 40                // row stride (floats)
#define WROWS 8               // rows per warp slab (4 out + 4 halo)
#define WSTAGE (WROWS * SMW)  // 320 floats = 1280 B per stage
#define NSLOT 9               // 8*36/32
#define CPERCTA 32
#define NSTAGE 4
#define PFD 3                 // prefetch distance (channels)

__device__ __forceinline__ void cp_async4(uint32_t saddr, const void* gaddr, int src_size) {
    asm volatile("cp.async.ca.shared.global [%0], [%1], 4, %2;"
                 :: "r"(saddr), "l"(gaddr), "r"(src_size));
}
__device__ __forceinline__ void cp_commit() {
    asm volatile("cp.async.commit_group;");
}
template <int N>
__device__ __forceinline__ void cp_wait() {
    asm volatile("cp.async.wait_group %0;" :: "n"(N));
}

__device__ __forceinline__ uint64_t lds64(uint32_t a) {
    uint64_t v; asm volatile("ld.shared.b64 %0, [%1];" : "=l"(v) : "r"(a)); return v;
}
__device__ __forceinline__ void ffma2(uint64_t& d, uint64_t a, uint64_t b) {
    asm("fma.rn.f32x2 %0, %1, %2, %0;" : "+l"(d) : "l"(a), "l"(b));
}
__device__ __forceinline__ uint64_t addf32x2(uint64_t a, uint64_t b) {
    uint64_t r; asm("add.rn.f32x2 %0, %1, %2;" : "=l"(r) : "l"(a), "l"(b)); return r;
}
__device__ __forceinline__ uint64_t pack2(uint32_t lo, uint32_t hi) {
    uint64_t r; asm("mov.b64 %0, {%1, %2};" : "=l"(r) : "r"(lo), "r"(hi)); return r;
}
__device__ __forceinline__ void unpack2(uint64_t v, uint32_t& lo, uint32_t& hi) {
    asm("mov.b64 {%0, %1}, %2;" : "=r"(lo), "=r"(hi) : "l"(v));
}

__global__ __launch_bounds__(128, 3)
void dynconv5x5_kernel(const float* __restrict__ x,
                       const float* __restrict__ wgt,
                       float* __restrict__ out) {
    // [warp][stage][slab]
    __shared__ float sm[4][NSTAGE][WSTAGE];

    const int tid  = threadIdx.x;
    const int wid  = tid >> 5;
    const int lane = tid & 31;
    const int qx   = lane & 15;    // 16 quads along W
    const int qy   = lane >> 4;    // 2 quad-rows per warp
    const int w0   = blockIdx.x * TW;
    const int h0   = blockIdx.y * TH;
    const int z    = blockIdx.z;
    const int b    = z >> 1;
    const int c0   = (z & 1) * CPERCTA;

    const int slab0 = h0 + wid * 4;      // warp's first output row
    const int oh    = slab0 + qy * 2;    // thread quad top row
    const int ow    = w0 + qx * 2;       // even -> 8B aligned

    // ---- quad weights as packed f32x2 pairs (100 regs), reused over 32 channels
    uint64_t wt[25], wb[25];
#pragma unroll
    for (int k = 0; k < 25; k++) {
        const float* wp = &wgt[(((size_t)k * BB + b) * HH_DIM + oh) * WW_DIM + ow];
        wt[k] = *(const uint64_t*)(wp);
        wb[k] = *(const uint64_t*)(wp + WW_DIM);
    }

    // ---- warp-private staging slots: 8 rows x 36 cols = 288 = 32 lanes x 9
    int xoff[NSLOT];
    int ssz [NSLOT];
    int soff[NSLOT];   // bytes within one stage
#pragma unroll
    for (int j = 0; j < NSLOT; j++) {
        int i  = lane + j * 32;
        int r  = i / SMCOLS;
        int cc = i - r * SMCOLS;
        int gh = slab0 + r - 2;
        int gw = w0 + cc - 2;
        bool v = gh >= 0 && gh < HH_DIM && gw >= 0 && gw < WW_DIM;
        xoff[j] = gh * WW_DIM + gw;
        ssz[j]  = v ? 4 : 0;               // src-size 0 => zero-fill (border pad)
        soff[j] = (r * SMW + cc) * 4;
    }

    const float* xc = x   + ((size_t)b * 64 + c0) * HW;
    float*       ob = out + (((size_t)b * 64 + c0) * HW) + oh * WW_DIM + ow;

    const uint32_t wbase = (uint32_t)__cvta_generic_to_shared(&sm[wid][0][0]);
    const uint32_t cbase = wbase + ((qy * 2) * SMW + qx * 2) * 4;  // compute lane base

    // ---- prologue: stage channels 0..PFD-1 into stages 0..PFD-1
#pragma unroll
    for (int p = 0; p < PFD; p++) {
        const float* xp = xc + (size_t)p * HW;
        const uint32_t sp = wbase + p * (WSTAGE * 4);
#pragma unroll
        for (int j = 0; j < NSLOT; j++)
            cp_async4(sp + soff[j], xp + xoff[j], ssz[j]);
        cp_commit();
    }

#pragma unroll 4
    for (int c = 0; c < CPERCTA; c++) {
        if (c + PFD < CPERCTA) cp_wait<PFD - 1>(); else cp_wait<0>();
        __syncwarp(0xffffffffu);   // publish this warp's staged channel c

        const uint32_t sbase = cbase + (c & (NSTAGE - 1)) * (WSTAGE * 4);

        // ---- 25 taps x 4 px via packed f32x2, 4 accumulator chains
        uint64_t at_e = 0, at_o = 0, ab_e = 0, ab_o = 0;
#pragma unroll
        for (int r = 0; r < 6; r++) {
            uint32_t base = sbase + r * (SMW * 4);
            uint64_t p0 = lds64(base);        // {x0,x1}
            uint64_t p2 = lds64(base + 8);    // {x2,x3}
            uint64_t p4 = lds64(base + 16);   // {x4,x5}
            uint32_t x0, x1, x2, x3, x4, x5;
            unpack2(p0, x0, x1);
            unpack2(p2, x2, x3);
            unpack2(p4, x4, x5);
            uint64_t p1 = pack2(x1, x2);
            uint64_t p3 = pack2(x3, x4);
            uint64_t P[5] = {p0, p1, p2, p3, p4};
            if (r < 5) {
#pragma unroll
                for (int ww = 0; ww < 5; ww++) {
                    int k = r * 5 + ww;
                    ffma2((k & 1) ? at_o : at_e, P[ww], wt[k]);
                }
            }
            if (r >= 1) {
#pragma unroll
                for (int ww = 0; ww < 5; ww++) {
                    int k = (r - 1) * 5 + ww;
                    ffma2((k & 1) ? ab_o : ab_e, P[ww], wb[k]);
                }
            }
        }

        float* o = ob + (size_t)c * HW;
        *(uint64_t*)(o)          = addf32x2(at_e, at_o);
        *(uint64_t*)(o + WW_DIM) = addf32x2(ab_e, ab_o);

        // stage channel c+PFD into its ring slot (stage reuse is guarded by
        // the syncwarps between: readers of that stage finished >=1 iter ago)
        if (c + PFD < CPERCTA) {
            const float* xn = xc + (size_t)(c + PFD) * HW;
            const uint32_t sn = wbase + ((c + PFD) & (NSTAGE - 1)) * (WSTAGE * 4);
#pragma unroll
            for (int j = 0; j < NSLOT; j++)
                cp_async4(sn + soff[j], xn + xoff[j], ssz[j]);
            cp_commit();
        }
    }
}

extern "C" void kernel_launch(void* const* d_in, const int* in_sizes, int n_in,
                              void* d_out, int out_size) {
    const float* x   = (const float*)d_in[0];
    const float* wgt = (const float*)d_in[1];
    float*       out = (float*)d_out;

    dim3 grid(WW_DIM / TW, HH_DIM / TH, BB * 2);   // 2048 blocks
    dim3 block(128);
    dynconv5x5_kernel<<<grid, block>>>(x, wgt, out);
}

// round 9
// speedup vs baseline: 1.2549x; 1.2254x over previous
#include <cuda_runtime.h>
#include <cuda_bf16.h>
#include <cstdint>

// Per-pixel dynamic 5x5 conv, channel-shared taps.
// x: [B=8, C=64, H=256, W=256] f32; w: [25, B, 1, H, W] f32
//
// Warp-private 4-stage pipelines (no __syncthreads in the loop), 2x2 quad per
// thread, 100 weight regs as packed f32x2, FFMA2 math. Staging now uses
// 16-byte cp.async.cg: each warp-stage is exactly 8 rows x 40 floats = 80
// float4 slots (3 LDGSTS/warp/channel instead of 9), L1-bypassed.

#define BB 8
#define HW 65536
#define HH_DIM 256
#define WW_DIM 256
#define TH 16
#define TW 32
#define SMW 40                // row stride (floats) == 10 float4, fully staged
#define WROWS 8               // rows per warp slab (4 out + 4 halo)
#define WSTAGE (WROWS * SMW)  // 320 floats = 80 float4 per stage
#define NSLOT4 80             // float4 slots per stage
#define CPERCTA 32
#define NSTAGE 4
#define PFD 3                 // prefetch distance (channels)

__device__ __forceinline__ void cp_async16(uint32_t saddr, const void* gaddr, int src_size) {
    asm volatile("cp.async.cg.shared.global [%0], [%1], 16, %2;"
                 :: "r"(saddr), "l"(gaddr), "r"(src_size));
}
__device__ __forceinline__ void cp_commit() {
    asm volatile("cp.async.commit_group;");
}
template <int N>
__device__ __forceinline__ void cp_wait() {
    asm volatile("cp.async.wait_group %0;" :: "n"(N));
}

__device__ __forceinline__ uint64_t lds64(uint32_t a) {
    uint64_t v; asm volatile("ld.shared.b64 %0, [%1];" : "=l"(v) : "r"(a)); return v;
}
__device__ __forceinline__ void ffma2(uint64_t& d, uint64_t a, uint64_t b) {
    asm("fma.rn.f32x2 %0, %1, %2, %0;" : "+l"(d) : "l"(a), "l"(b));
}
__device__ __forceinline__ uint64_t addf32x2(uint64_t a, uint64_t b) {
    uint64_t r; asm("add.rn.f32x2 %0, %1, %2;" : "=l"(r) : "l"(a), "l"(b)); return r;
}
__device__ __forceinline__ uint64_t pack2(uint32_t lo, uint32_t hi) {
    uint64_t r; asm("mov.b64 %0, {%1, %2};" : "=l"(r) : "r"(lo), "r"(hi)); return r;
}
__device__ __forceinline__ void unpack2(uint64_t v, uint32_t& lo, uint32_t& hi) {
    asm("mov.b64 {%0, %1}, %2;" : "=r"(lo), "=r"(hi) : "l"(v));
}

__global__ __launch_bounds__(128, 3)
void dynconv5x5_kernel(const float* __restrict__ x,
                       const float* __restrict__ wgt,
                       float* __restrict__ out) {
    // [warp][stage][slab]
    __shared__ float sm[4][NSTAGE][WSTAGE];

    const int tid  = threadIdx.x;
    const int wid  = tid >> 5;
    const int lane = tid & 31;
    const int qx   = lane & 15;
    const int qy   = lane >> 4;
    const int w0   = blockIdx.x * TW;
    const int h0   = blockIdx.y * TH;
    const int z    = blockIdx.z;
    const int b    = z >> 1;
    const int c0   = (z & 1) * CPERCTA;

    const int slab0 = h0 + wid * 4;      // warp's first output row
    const int oh    = slab0 + qy * 2;
    const int ow    = w0 + qx * 2;

    // ---- quad weights as packed f32x2 pairs (100 regs)
    uint64_t wt[25], wb[25];
#pragma unroll
    for (int k = 0; k < 25; k++) {
        const float* wp = &wgt[(((size_t)k * BB + b) * HH_DIM + oh) * WW_DIM + ow];
        wt[k] = *(const uint64_t*)(wp);
        wb[k] = *(const uint64_t*)(wp + WW_DIM);
    }

    // ---- 16B staging slots: 80 float4 = 8 rows x 10; col c <-> gw w0-4+c
    // lanes 0..31 take slots lane, lane+32; lanes 0..15 also slot lane+64.
    int xoff[3];   // gmem float offset of the 16B chunk
    int ssz [3];   // 16 or 0 (zfill for border / H-halo)
    int soff[3];   // byte offset within stage
    int nslot_here = (lane < 16) ? 3 : 2;
#pragma unroll
    for (int j = 0; j < 3; j++) {
        int i    = lane + j * 32;      // slot id 0..79
        int r    = i / 10;
        int col4 = i - r * 10;
        int gh = slab0 + r - 2;
        int gw = w0 - 4 + col4 * 4;    // 16B-aligned, fully in or out of [0,256)
        bool v = (i < NSLOT4) && gh >= 0 && gh < HH_DIM && gw >= 0 && gw < WW_DIM;
        xoff[j] = gh * WW_DIM + gw;
        ssz[j]  = v ? 16 : 0;
        soff[j] = (r * SMW + col4 * 4) * 4;
    }

    const float* xc = x   + ((size_t)b * 64 + c0) * HW;
    float*       ob = out + (((size_t)b * 64 + c0) * HW) + oh * WW_DIM + ow;

    const uint32_t wbase = (uint32_t)__cvta_generic_to_shared(&sm[wid][0][0]);
    // compute base: output col ow maps to sm col 2*qx+2 (even -> 8B aligned)
    const uint32_t cbase = wbase + ((qy * 2) * SMW + (qx * 2 + 2)) * 4;

    // ---- prologue: stage channels 0..PFD-1
#pragma unroll
    for (int p = 0; p < PFD; p++) {
        const float* xp = xc + (size_t)p * HW;
        const uint32_t sp = wbase + p * (WSTAGE * 4);
        cp_async16(sp + soff[0], xp + xoff[0], ssz[0]);
        cp_async16(sp + soff[1], xp + xoff[1], ssz[1]);
        if (nslot_here == 3) cp_async16(sp + soff[2], xp + xoff[2], ssz[2]);
        cp_commit();
    }

#pragma unroll 4
    for (int c = 0; c < CPERCTA; c++) {
        if (c + PFD < CPERCTA) cp_wait<PFD - 1>(); else cp_wait<0>();
        __syncwarp(0xffffffffu);

        const uint32_t sbase = cbase + (c & (NSTAGE - 1)) * (WSTAGE * 4);

        uint64_t at_e = 0, at_o = 0, ab_e = 0, ab_o = 0;
#pragma unroll
        for (int r = 0; r < 6; r++) {
            uint32_t base = sbase + r * (SMW * 4);
            uint64_t p0 = lds64(base);
            uint64_t p2 = lds64(base + 8);
            uint64_t p4 = lds64(base + 16);
            uint32_t x0, x1, x2, x3, x4, x5;
            unpack2(p0, x0, x1);
            unpack2(p2, x2, x3);
            unpack2(p4, x4, x5);
            uint64_t p1 = pack2(x1, x2);
            uint64_t p3 = pack2(x3, x4);
            uint64_t P[5] = {p0, p1, p2, p3, p4};
            if (r < 5) {
#pragma unroll
                for (int ww = 0; ww < 5; ww++) {
                    int k = r * 5 + ww;
                    ffma2((k & 1) ? at_o : at_e, P[ww], wt[k]);
                }
            }
            if (r >= 1) {
#pragma unroll
                for (int ww = 0; ww < 5; ww++) {
                    int k = (r - 1) * 5 + ww;
                    ffma2((k & 1) ? ab_o : ab_e, P[ww], wb[k]);
                }
            }
        }

        float* o = ob + (size_t)c * HW;
        *(uint64_t*)(o)          = addf32x2(at_e, at_o);
        *(uint64_t*)(o + WW_DIM) = addf32x2(ab_e, ab_o);

        if (c + PFD < CPERCTA) {
            const float* xn = xc + (size_t)(c + PFD) * HW;
            const uint32_t sn = wbase + ((c + PFD) & (NSTAGE - 1)) * (WSTAGE * 4);
            cp_async16(sn + soff[0], xn + xoff[0], ssz[0]);
            cp_async16(sn + soff[1], xn + xoff[1], ssz[1]);
            if (nslot_here == 3) cp_async16(sn + soff[2], xn + xoff[2], ssz[2]);
            cp_commit();
        }
    }
}

extern "C" void kernel_launch(void* const* d_in, const int* in_sizes, int n_in,
                              void* d_out, int out_size) {
    const float* x   = (const float*)d_in[0];
    const float* wgt = (const float*)d_in[1];
    float*       out = (float*)d_out;

    dim3 grid(WW_DIM / TW, HH_DIM / TH, BB * 2);   // 2048 blocks
    dim3 block(128);
    dynconv5x5_kernel<<<grid, block>>>(x, wgt, out);
}

// round 10
// speedup vs baseline: 1.2830x; 1.0224x over previous
#include <cuda_runtime.h>
#include <cuda_bf16.h>
#include <cstdint>

// Per-pixel dynamic 5x5 conv, channel-shared taps.
// x: [B=8, C=64, H=256, W=256] f32; w: [25, B, 1, H, W] f32
//
// Warp-private 4-stage cp.async.cg pipelines (16B staging, no __syncthreads),
// 2x2 quad/thread. Tap math split by x-offset parity: even-offset taps use
// FFMA2 on naturally-aligned smem pairs (p0,p2,p4); odd-offset taps use scalar
// FFMA on the unpacked halves. Zero register re-packing -> no MOV tax.

#define BB 8
#define HW 65536
#define HH_DIM 256
#define WW_DIM 256
#define TH 16
#define TW 32
#define SMW 40                // row stride (floats) == 10 float4, fully staged
#define WROWS 8               // rows per warp slab (4 out + 4 halo)
#define WSTAGE (WROWS * SMW)  // 320 floats = 80 float4 per stage
#define NSLOT4 80
#define CPERCTA 32
#define NSTAGE 4
#define PFD 3

__device__ __forceinline__ void cp_async16(uint32_t saddr, const void* gaddr, int src_size) {
    asm volatile("cp.async.cg.shared.global [%0], [%1], 16, %2;"
                 :: "r"(saddr), "l"(gaddr), "r"(src_size));
}
__device__ __forceinline__ void cp_commit() {
    asm volatile("cp.async.commit_group;");
}
template <int N>
__device__ __forceinline__ void cp_wait() {
    asm volatile("cp.async.wait_group %0;" :: "n"(N));
}

__device__ __forceinline__ uint64_t lds64(uint32_t a) {
    uint64_t v; asm volatile("ld.shared.b64 %0, [%1];" : "=l"(v) : "r"(a)); return v;
}
__device__ __forceinline__ void ffma2(uint64_t& d, uint64_t a, uint64_t b) {
    asm("fma.rn.f32x2 %0, %1, %2, %0;" : "+l"(d) : "l"(a), "l"(b));
}
__device__ __forceinline__ uint64_t addf32x2(uint64_t a, uint64_t b) {
    uint64_t r; asm("add.rn.f32x2 %0, %1, %2;" : "=l"(r) : "l"(a), "l"(b)); return r;
}
// unpack into independent scalars (never re-packed -> ptxas can alias, no MOV)
__device__ __forceinline__ void unpack2f(uint64_t v, float& lo, float& hi) {
    asm("mov.b64 {%0, %1}, %2;" : "=f"(lo), "=f"(hi) : "l"(v));
}

__global__ __launch_bounds__(128, 3)
void dynconv5x5_kernel(const float* __restrict__ x,
                       const float* __restrict__ wgt,
                       float* __restrict__ out) {
    __shared__ float sm[4][NSTAGE][WSTAGE];

    const int tid  = threadIdx.x;
    const int wid  = tid >> 5;
    const int lane = tid & 31;
    const int qx   = lane & 15;
    const int qy   = lane >> 4;
    const int w0   = blockIdx.x * TW;
    const int h0   = blockIdx.y * TH;
    const int z    = blockIdx.z;
    const int b    = z >> 1;
    const int c0   = (z & 1) * CPERCTA;

    const int slab0 = h0 + wid * 4;
    const int oh    = slab0 + qy * 2;
    const int ow    = w0 + qx * 2;

    // ---- weights, split by tap x-offset parity (100 regs total)
    // even ww (0,2,4): packed pair {w(px0), w(px1)} for FFMA2
    // odd  ww (1,3):   scalar halves for scalar FFMA
    uint64_t wtp[15], wbp[15];               // [r*3 + ww/2]
    float wtsl[10], wtsh[10], wbsl[10], wbsh[10];  // [r*2 + (ww==3)]
#pragma unroll
    for (int r = 0; r < 5; r++) {
#pragma unroll
        for (int ww = 0; ww < 5; ww++) {
            const float* wp = &wgt[(((size_t)(r * 5 + ww) * BB + b) * HH_DIM + oh) * WW_DIM + ow];
            uint64_t t  = *(const uint64_t*)(wp);
            uint64_t bo = *(const uint64_t*)(wp + WW_DIM);
            if ((ww & 1) == 0) {
                wtp[r * 3 + ww / 2] = t;
                wbp[r * 3 + ww / 2] = bo;
            } else {
                int j = r * 2 + (ww == 3);
                unpack2f(t,  wtsl[j], wtsh[j]);
                unpack2f(bo, wbsl[j], wbsh[j]);
            }
        }
    }

    // ---- 16B staging slots: 80 float4 = 8 rows x 10; col c <-> gw w0-4+c
    int xoff[3];
    int ssz [3];
    int soff[3];
    int nslot_here = (lane < 16) ? 3 : 2;
#pragma unroll
    for (int j = 0; j < 3; j++) {
        int i    = lane + j * 32;
        int r    = i / 10;
        int col4 = i - r * 10;
        int gh = slab0 + r - 2;
        int gw = w0 - 4 + col4 * 4;
        bool v = (i < NSLOT4) && gh >= 0 && gh < HH_DIM && gw >= 0 && gw < WW_DIM;
        xoff[j] = gh * WW_DIM + gw;
        ssz[j]  = v ? 16 : 0;
        soff[j] = (r * SMW + col4 * 4) * 4;
    }

    const float* xc = x   + ((size_t)b * 64 + c0) * HW;
    float*       ob = out + (((size_t)b * 64 + c0) * HW) + oh * WW_DIM + ow;

    const uint32_t wbase = (uint32_t)__cvta_generic_to_shared(&sm[wid][0][0]);
    const uint32_t cbase = wbase + ((qy * 2) * SMW + (qx * 2 + 2)) * 4;

    // ---- prologue: stage channels 0..PFD-1
#pragma unroll
    for (int p = 0; p < PFD; p++) {
        const float* xp = xc + (size_t)p * HW;
        const uint32_t sp = wbase + p * (WSTAGE * 4);
        cp_async16(sp + soff[0], xp + xoff[0], ssz[0]);
        cp_async16(sp + soff[1], xp + xoff[1], ssz[1]);
        if (nslot_here == 3) cp_async16(sp + soff[2], xp + xoff[2], ssz[2]);
        cp_commit();
    }

#pragma unroll 4
    for (int c = 0; c < CPERCTA; c++) {
        if (c + PFD < CPERCTA) cp_wait<PFD - 1>(); else cp_wait<0>();
        __syncwarp(0xffffffffu);

        const uint32_t sbase = cbase + (c & (NSTAGE - 1)) * (WSTAGE * 4);

        // accumulators: 2 packed chains + 2 scalar chains per pixel row
        uint64_t atp = 0, atq = 0, abp = 0, abq = 0;
        float ats0 = 0.f, ats1 = 0.f, abs0 = 0.f, abs1 = 0.f;
#pragma unroll
        for (int r = 0; r < 6; r++) {
            uint32_t base = sbase + r * (SMW * 4);
            uint64_t p0 = lds64(base);        // {x0,x1}
            uint64_t p2 = lds64(base + 8);    // {x2,x3}
            uint64_t p4 = lds64(base + 16);   // {x4,x5}
            float x0, x1, x2, x3, x4, x5;
            unpack2f(p0, x0, x1);
            unpack2f(p2, x2, x3);
            unpack2f(p4, x4, x5);
            if (r < 5) {
                ffma2(atp, p0, wtp[r * 3 + 0]);
                ffma2(atq, p2, wtp[r * 3 + 1]);
                ffma2(atp, p4, wtp[r * 3 + 2]);
                ats0 = fmaf(x1, wtsl[r * 2 + 0], ats0);
                ats1 = fmaf(x2, wtsh[r * 2 + 0], ats1);
                ats0 = fmaf(x3, wtsl[r * 2 + 1], ats0);
                ats1 = fmaf(x4, wtsh[r * 2 + 1], ats1);
            }
            if (r >= 1) {
                int q = r - 1;
                ffma2(abp, p0, wbp[q * 3 + 0]);
                ffma2(abq, p2, wbp[q * 3 + 1]);
                ffma2(abp, p4, wbp[q * 3 + 2]);
                abs0 = fmaf(x1, wbsl[q * 2 + 0], abs0);
                abs1 = fmaf(x2, wbsh[q * 2 + 0], abs1);
                abs0 = fmaf(x3, wbsl[q * 2 + 1], abs0);
                abs1 = fmaf(x4, wbsh[q * 2 + 1], abs1);
            }
        }

        float tl, th, bl, bh;
        unpack2f(addf32x2(atp, atq), tl, th);
        unpack2f(addf32x2(abp, abq), bl, bh);

        float* o = ob + (size_t)c * HW;
        *(float2*)(o)          = make_float2(tl + ats0, th + ats1);
        *(float2*)(o + WW_DIM) = make_float2(bl + abs0, bh + abs1);

        if (c + PFD < CPERCTA) {
            const float* xn = xc + (size_t)(c + PFD) * HW;
            const uint32_t sn = wbase + ((c + PFD) & (NSTAGE - 1)) * (WSTAGE * 4);
            cp_async16(sn + soff[0], xn + xoff[0], ssz[0]);
            cp_async16(sn + soff[1], xn + xoff[1], ssz[1]);
            if (nslot_here == 3) cp_async16(sn + soff[2], xn + xoff[2], ssz[2]);
            cp_commit();
        }
    }
}

extern "C" void kernel_launch(void* const* d_in, const int* in_sizes, int n_in,
                              void* d_out, int out_size) {
    const float* x   = (const float*)d_in[0];
    const float* wgt = (const float*)d_in[1];
    float*       out = (float*)d_out;

    dim3 grid(WW_DIM / TW, HH_DIM / TH, BB * 2);   // 2048 blocks
    dim3 block(128);
    dynconv5x5_kernel<<<grid, block>>>(x, wgt, out);
}

// round 11
// speedup vs baseline: 1.3217x; 1.0302x over previous
#include <cuda_runtime.h>
#include <cuda_bf16.h>
#include <cstdint>

// Per-pixel dynamic 5x5 conv, channel-shared taps.
// x: [B=8, C=64, H=256, W=256] f32; w: [25, B, 1, H, W] f32
//
// Warp-private 4-stage cp.async.cg pipelines, 2x2 quad/thread, parity-split
// FFMA2/FFMA math. NEW: fully software-pipelined — rolling 3-row register
// window (load row r+2 while computing row r), cross-channel row prefetch
// (rows 0-1 of channel c+1 load during rows 4-5 of channel c), mid-channel
// wait+syncwarp, branchless clamped staging.

#define BB 8
#define HW 65536
#define HH_DIM 256
#define WW_DIM 256
#define TH 16
#define TW 32
#define SMW 40                // row stride (floats) == 10 float4, fully staged
#define WROWS 8               // rows per warp slab (4 out + 4 halo)
#define WSTAGE (WROWS * SMW)  // 320 floats per stage
#define NSLOT4 80
#define CPERCTA 32
#define PFD 3                 // prefetch distance (channels), NSTAGE=4 ring

__device__ __forceinline__ void cp_async16(uint32_t saddr, const void* gaddr, int src_size) {
    asm volatile("cp.async.cg.shared.global [%0], [%1], 16, %2;"
                 :: "r"(saddr), "l"(gaddr), "r"(src_size));
}
__device__ __forceinline__ void cp_commit() {
    asm volatile("cp.async.commit_group;");
}
template <int N>
__device__ __forceinline__ void cp_wait() {
    asm volatile("cp.async.wait_group %0;" :: "n"(N));
}

__device__ __forceinline__ uint64_t lds64(uint32_t a) {
    uint64_t v; asm volatile("ld.shared.b64 %0, [%1];" : "=l"(v) : "r"(a)); return v;
}
__device__ __forceinline__ void ffma2(uint64_t& d, uint64_t a, uint64_t b) {
    asm("fma.rn.f32x2 %0, %1, %2, %0;" : "+l"(d) : "l"(a), "l"(b));
}
__device__ __forceinline__ uint64_t addf32x2(uint64_t a, uint64_t b) {
    uint64_t r; asm("add.rn.f32x2 %0, %1, %2;" : "=l"(r) : "l"(a), "l"(b)); return r;
}
__device__ __forceinline__ void unpack2f(uint64_t v, float& lo, float& hi) {
    asm("mov.b64 {%0, %1}, %2;" : "=f"(lo), "=f"(hi) : "l"(v));
}

__global__ __launch_bounds__(128, 3)
void dynconv5x5_kernel(const float* __restrict__ x,
                       const float* __restrict__ wgt,
                       float* __restrict__ out) {
    __shared__ float sm[4][4][WSTAGE];   // [warp][stage][slab]

    const int tid  = threadIdx.x;
    const int wid  = tid >> 5;
    const int lane = tid & 31;
    const int qx   = lane & 15;
    const int qy   = lane >> 4;
    const int w0   = blockIdx.x * TW;
    const int h0   = blockIdx.y * TH;
    const int z    = blockIdx.z;
    const int b    = z >> 1;
    const int c0   = (z & 1) * CPERCTA;

    const int slab0 = h0 + wid * 4;
    const int oh    = slab0 + qy * 2;
    const int ow    = w0 + qx * 2;

    // ---- weights, split by tap x-offset parity (100 regs total)
    uint64_t wtp[15], wbp[15];                      // even-ww packed pairs
    float wtsl[10], wtsh[10], wbsl[10], wbsh[10];   // odd-ww scalar halves
#pragma unroll
    for (int r = 0; r < 5; r++) {
#pragma unroll
        for (int ww = 0; ww < 5; ww++) {
            const float* wp = &wgt[(((size_t)(r * 5 + ww) * BB + b) * HH_DIM + oh) * WW_DIM + ow];
            uint64_t t  = *(const uint64_t*)(wp);
            uint64_t bo = *(const uint64_t*)(wp + WW_DIM);
            if ((ww & 1) == 0) {
                wtp[r * 3 + ww / 2] = t;
                wbp[r * 3 + ww / 2] = bo;
            } else {
                int j = r * 2 + (ww == 3);
                unpack2f(t,  wtsl[j], wtsh[j]);
                unpack2f(bo, wbsl[j], wbsh[j]);
            }
        }
    }

    // ---- 16B staging slots (80 float4 = 8 rows x 10; col c <-> gw w0-4+c)
    int xoff[3];
    int ssz [3];
    int soff[3];
    int nslot_here = (lane < 16) ? 3 : 2;
#pragma unroll
    for (int j = 0; j < 3; j++) {
        int i    = lane + j * 32;
        int r    = i / 10;
        int col4 = i - r * 10;
        int gh = slab0 + r - 2;
        int gw = w0 - 4 + col4 * 4;
        bool v = (i < NSLOT4) && gh >= 0 && gh < HH_DIM && gw >= 0 && gw < WW_DIM;
        xoff[j] = gh * WW_DIM + gw;
        ssz[j]  = v ? 16 : 0;
        soff[j] = (r * SMW + col4 * 4) * 4;
    }

    const float* xc = x   + ((size_t)b * 64 + c0) * HW;
    float*       ob = out + (((size_t)b * 64 + c0) * HW) + oh * WW_DIM + ow;

    const uint32_t wbase = (uint32_t)__cvta_generic_to_shared(&sm[wid][0][0]);
    const uint32_t cbase = wbase + ((qy * 2) * SMW + (qx * 2 + 2)) * 4;

    // ---- prologue: stage channels 0..2
#pragma unroll
    for (int p = 0; p < PFD; p++) {
        const float* xp = xc + (size_t)p * HW;
        const uint32_t sp = wbase + p * (WSTAGE * 4);
        cp_async16(sp + soff[0], xp + xoff[0], ssz[0]);
        cp_async16(sp + soff[1], xp + xoff[1], ssz[1]);
        if (nslot_here == 3) cp_async16(sp + soff[2], xp + xoff[2], ssz[2]);
        cp_commit();
    }
    cp_wait<PFD - 1>();
    __syncwarp(0xffffffffu);

    // rolling 3-row register window; preload rows 0,1 of channel 0
    uint64_t rp[3][3];
    {
        const uint32_t s0 = cbase;   // stage 0
#pragma unroll
        for (int r = 0; r < 2; r++) {
            uint32_t a = s0 + r * (SMW * 4);
            rp[r][0] = lds64(a);
            rp[r][1] = lds64(a + 8);
            rp[r][2] = lds64(a + 16);
        }
    }

#pragma unroll 4
    for (int c = 0; c < CPERCTA; c++) {
        const uint32_t sc = cbase + (c & 3) * (WSTAGE * 4);
        const uint32_t sn = cbase + ((c + 1) & 3) * (WSTAGE * 4);
        // clamped prefetch channel: duplicate stores for c>=29 land in stages
        // that are never read again (ring schedule verified)
        int cs = c + PFD; if (cs > CPERCTA - 1) cs = CPERCTA - 1;
        const float*  xs = xc + (size_t)cs * HW;
        const uint32_t ss = wbase + (cs & 3) * (WSTAGE * 4) +
                            (cbase - cbase);  // stage base (warp frame)
        const uint32_t ssb = wbase + (cs & 3) * (WSTAGE * 4);
        (void)ss;

        uint64_t atp = 0, atq = 0, abp = 0, abq = 0;
        float ats0 = 0.f, ats1 = 0.f, abs0 = 0.f, abs1 = 0.f;

#pragma unroll
        for (int r = 0; r < 6; r++) {
            // -- issue loads for row r+2 (this channel) or rows 0/1 of next
            if (r < 4) {
                int s2 = (r + 2) % 3;
                uint32_t a = sc + (r + 2) * (SMW * 4);
                rp[s2][0] = lds64(a);
                rp[s2][1] = lds64(a + 8);
                rp[s2][2] = lds64(a + 16);
            }
            // -- scatter staging issues for channel cs
            if (r == 2) cp_async16(ssb + soff[0], xs + xoff[0], ssz[0]);
            if (r == 3) {
                cp_async16(ssb + soff[1], xs + xoff[1], ssz[1]);
                if (nslot_here == 3) cp_async16(ssb + soff[2], xs + xoff[2], ssz[2]);
                cp_commit();
            }

            // -- compute row r from slot r%3
            int s = r % 3;
            uint64_t p0 = rp[s][0], p2 = rp[s][1], p4 = rp[s][2];
            float x0, x1, x2, x3, x4, x5;
            unpack2f(p0, x0, x1);
            unpack2f(p2, x2, x3);
            unpack2f(p4, x4, x5);
            if (r < 5) {
                ffma2(atp, p0, wtp[r * 3 + 0]);
                ffma2(atq, p2, wtp[r * 3 + 1]);
                ffma2(atp, p4, wtp[r * 3 + 2]);
                ats0 = fmaf(x1, wtsl[r * 2 + 0], ats0);
                ats1 = fmaf(x2, wtsh[r * 2 + 0], ats1);
                ats0 = fmaf(x3, wtsl[r * 2 + 1], ats0);
                ats1 = fmaf(x4, wtsh[r * 2 + 1], ats1);
            }
            if (r >= 1) {
                int q = r - 1;
                ffma2(abp, p0, wbp[q * 3 + 0]);
                ffma2(abq, p2, wbp[q * 3 + 1]);
                ffma2(abp, p4, wbp[q * 3 + 2]);
                abs0 = fmaf(x1, wbsl[q * 2 + 0], abs0);
                abs1 = fmaf(x2, wbsh[q * 2 + 0], abs1);
                abs0 = fmaf(x3, wbsl[q * 2 + 1], abs0);
                abs1 = fmaf(x4, wbsh[q * 2 + 1], abs1);
            }

            // -- mid-channel publish point: channel c+1's stage becomes readable
            if (r == 3) {
                cp_wait<PFD - 1>();
                __syncwarp(0xffffffffu);
            }
            // -- cross-channel prefetch: rows 0,1 of channel c+1
            if (r >= 4) {
                int s2 = (r + 2) % 3;   // == (r-4)%3, seamless for next channel
                uint32_t a = sn + (r - 4) * (SMW * 4);
                rp[s2][0] = lds64(a);
                rp[s2][1] = lds64(a + 8);
                rp[s2][2] = lds64(a + 16);
            }
        }

        float tl, th, bl, bh;
        unpack2f(addf32x2(atp, atq), tl, th);
        unpack2f(addf32x2(abp, abq), bl, bh);

        float* o = ob + (size_t)c * HW;
        *(float2*)(o)          = make_float2(tl + ats0, th + ats1);
        *(float2*)(o + WW_DIM) = make_float2(bl + abs0, bh + abs1);
    }
}

extern "C" void kernel_launch(void* const* d_in, const int* in_sizes, int n_in,
                              void* d_out, int out_size) {
    const float* x   = (const float*)d_in[0];
    const float* wgt = (const float*)d_in[1];
    float*       out = (float*)d_out;

    dim3 grid(WW_DIM / TW, HH_DIM / TH, BB * 2);   // 2048 blocks
    dim3 block(128);
    dynconv5x5_kernel<<<grid, block>>>(x, wgt, out);
}